// round 5
// baseline (speedup 1.0000x reference)
#include <cuda_runtime.h>
#include <cuda_bf16.h>

#define NUM_CHIPS 4
#define N_EXPERTS 32
#define TOP_K 4
#define SEQ 1024
#define HIDDEN 2048
#define MAX_TOK 1024
#define META_LEN 8
#define NPC (SEQ * TOP_K)            /* 4096 assignments per chip  */
#define NA (NUM_CHIPS * NPC)         /* 16384 total assignments    */
#define NROWS (N_EXPERTS * MAX_TOK)  /* 32768 output rows          */

#define V4_PER_ROW (HIDDEN / 4)      /* 512 float4 per row */
#define COPY_BLOCKS 1024
#define COPY_THREADS 256             /* 8 warps/block -> 8192 warps */
#define ROWS_PER_WARP 4              /* 8192 * 4 = 32768 rows       */

/* scratch — no allocations allowed */
__device__ int g_counts[NUM_CHIPS * N_EXPERTS];
__device__ int g_rank[NA];       /* assignment -> stable rank within its chip+expert */
__device__ int g_srcrow[NROWS];  /* row -> source token row index, or -1             */

/* ------------------------------------------------------------------ */
/* Kernel 1: stable within-chip rank via warp intrinsics.
   One block per chip, 1024 threads; warp w owns assignments
   [w*128, w*128+128) in 4 rounds of 32 (lane order = flat order).      */
__global__ void __launch_bounds__(1024) k_rank(const int* __restrict__ indices) {
    __shared__ int wcount[32 * 33];   /* [warp][expert], 33-padded */
    __shared__ int woff[32 * 33];
    const int c = blockIdx.x;
    const int tid = threadIdx.x, w = tid >> 5, lane = tid & 31;

    for (int i = tid; i < 32 * 33; i += 1024) wcount[i] = 0;
    __syncthreads();

    int er[4], lr[4];
#pragma unroll
    for (int r = 0; r < 4; r++) {
        const int j = w * 128 + r * 32 + lane;          /* coalesced */
        const int e = indices[c * NPC + j];
        const unsigned mask = __match_any_sync(0xffffffffu, e);
        const int leader = __ffs(mask) - 1;
        const int prefix = __popc(mask & ((1u << lane) - 1u));
        int base = 0;
        if (lane == leader) base = atomicAdd(&wcount[w * 33 + e], __popc(mask));
        base = __shfl_sync(0xffffffffu, base, leader);
        er[r] = e; lr[r] = base + prefix;
    }
    __syncthreads();

    /* warp e scans wcount[*][e] across the 32 warps (lane = warp idx) */
    {
        const int e = w;
        const int val = wcount[lane * 33 + e];
        int incl = val;
#pragma unroll
        for (int d = 1; d < 32; d <<= 1) {
            int n = __shfl_up_sync(0xffffffffu, incl, d);
            if (lane >= d) incl += n;
        }
        woff[lane * 33 + e] = incl - val;
        if (lane == 31) g_counts[c * N_EXPERTS + e] = incl;
    }
    __syncthreads();

#pragma unroll
    for (int r = 0; r < 4; r++) {
        const int j = w * 128 + r * 32 + lane;
        g_rank[c * NPC + j] = woff[w * 33 + er[r]] + lr[r];
    }
}

/* ------------------------------------------------------------------ */
/* Kernel 2: offsets (inline) + row->src table + metadata + counters.
   Threads [0,16384): assignment role (filled rows).
   Threads [16384,49152): row role (tail rows -> -1).                  */
__global__ void __launch_bounds__(256) k_prep(const float* __restrict__ w,
                                              const int* __restrict__ indices,
                                              float* __restrict__ meta,
                                              float* __restrict__ out_cnt) {
    const int t = blockIdx.x * 256 + threadIdx.x;
    if (t < NA) {
        const int c = t >> 12, n = t & (NPC - 1);
        const int tok = n >> 2, kk = n & (TOP_K - 1);
        const int e = indices[t];                        /* coalesced */
        int off = 0;
#pragma unroll
        for (int cc = 0; cc < NUM_CHIPS - 1; cc++)
            if (cc < c) off += g_counts[cc * N_EXPERTS + e];
        const int row = e * MAX_TOK + off + g_rank[t];
        g_srcrow[row] = c * SEQ + tok;
        __nv_bfloat16 wb = __float2bfloat16(w[t]);      /* RNE, matches jnp */
        const int bits = (int)__bfloat16_as_short(wb);  /* sign-extended    */
        float4* m = (float4*)(meta + (size_t)row * META_LEN);
        m[0] = make_float4((float)c, (float)tok, (float)kk, (float)e);
        m[1] = make_float4((float)bits, 0.f, 0.f, 0.f);
        if (t < N_EXPERTS) {                             /* counters section */
            int tot = 0;
#pragma unroll
            for (int cc = 0; cc < NUM_CHIPS; cc++) tot += g_counts[cc * N_EXPERTS + t];
            out_cnt[t] = (float)tot;
        }
    } else {
        const int row = t - NA;
        if (row >= NROWS) return;
        const int e = row >> 10, r = row & (MAX_TOK - 1);
        int tot = 0;
#pragma unroll
        for (int cc = 0; cc < NUM_CHIPS; cc++) tot += g_counts[cc * N_EXPERTS + e];
        if (r < tot) return;                             /* filled above */
        g_srcrow[row] = -1;
        float4* m = (float4*)(meta + (size_t)row * META_LEN);
        const float4 neg = make_float4(-1.f, -1.f, -1.f, -1.f);
        m[0] = neg; m[1] = neg;
    }
}

/* ------------------------------------------------------------------ */
/* Kernel 3: row-per-warp streaming copy of the 256 MB buffer.
   One srcrow load per row (amortized ~1/32 LSU op per element),
   16 coalesced 512B warp-iterations per 8 KB row. Zero rows issue
   stores only (no load traffic at all).                               */
__global__ void __launch_bounds__(COPY_THREADS) k_copy(const float4* __restrict__ x4,
                                                       float4* __restrict__ buf4) {
    const unsigned gw = (blockIdx.x * COPY_THREADS + threadIdx.x) >> 5;  /* global warp */
    const unsigned lane = threadIdx.x & 31;

#pragma unroll
    for (int r = 0; r < ROWS_PER_WARP; r++) {
        const unsigned row = gw * ROWS_PER_WARP + r;
        const int s = __ldg(&g_srcrow[row]);
        float4* dst = buf4 + row * V4_PER_ROW + lane;
        if (s >= 0) {
            const float4* src = x4 + (unsigned)s * V4_PER_ROW + lane;
#pragma unroll
            for (int it = 0; it < 16; it++)
                dst[it * 32] = __ldg(&src[it * 32]);
        } else {
            const float4 z = make_float4(0.f, 0.f, 0.f, 0.f);
#pragma unroll
            for (int it = 0; it < 16; it++)
                dst[it * 32] = z;
        }
    }
}

/* ------------------------------------------------------------------ */
extern "C" void kernel_launch(void* const* d_in, const int* in_sizes, int n_in,
                              void* d_out, int out_size) {
    const float* x   = (const float*)d_in[0];
    const float* w   = (const float*)d_in[1];
    const int*   idx = (const int*)d_in[2];

    float* out  = (float*)d_out;
    float* buf  = out;                                                   /* 32*1024*2048 */
    float* meta = out + (size_t)NROWS * HIDDEN;                          /* 32*1024*8    */
    float* cnt  = meta + (size_t)NROWS * META_LEN;                       /* 32           */

    k_rank<<<NUM_CHIPS, 1024>>>(idx);
    k_prep<<<(NA + NROWS + 255) / 256, 256>>>(w, idx, meta, cnt);
    k_copy<<<COPY_BLOCKS, COPY_THREADS>>>((const float4*)x, (float4*)buf);
}

// round 6
// speedup vs baseline: 1.0064x; 1.0064x over previous
#include <cuda_runtime.h>
#include <cuda_bf16.h>

#define NUM_CHIPS 4
#define N_EXPERTS 32
#define TOP_K 4
#define SEQ 1024
#define HIDDEN 2048
#define MAX_TOK 1024
#define META_LEN 8
#define NPC (SEQ * TOP_K)            /* 4096 assignments per chip  */
#define NA (NUM_CHIPS * NPC)         /* 16384 total assignments    */
#define NROWS (N_EXPERTS * MAX_TOK)  /* 32768 output rows          */

#define V4_PER_ROW (HIDDEN / 4)      /* 512 float4 per row */
#define COPY_BLOCKS 1024
#define COPY_THREADS 256             /* 8 warps/block -> 8192 warps */
#define TOTAL_WARPS (COPY_BLOCKS * COPY_THREADS / 32)   /* 8192 */
#define ROWS_PER_WARP 4              /* 8192 * 4 = 32768 rows      */

/* scratch — no allocations allowed */
__device__ int g_counts[NUM_CHIPS * N_EXPERTS];
__device__ int g_rank[NA];       /* assignment -> stable rank within its chip+expert */
__device__ int g_srcrow[NROWS];  /* row -> source token row index, or -1             */

/* ------------------------------------------------------------------ */
/* Kernel 1: stable within-chip rank via warp intrinsics.
   One block per chip, 1024 threads; warp w owns assignments
   [w*128, w*128+128) in 4 rounds of 32 (lane order = flat order).      */
__global__ void __launch_bounds__(1024) k_rank(const int* __restrict__ indices) {
    __shared__ int wcount[32 * 33];   /* [warp][expert], 33-padded */
    __shared__ int woff[32 * 33];
    const int c = blockIdx.x;
    const int tid = threadIdx.x, w = tid >> 5, lane = tid & 31;

    for (int i = tid; i < 32 * 33; i += 1024) wcount[i] = 0;
    __syncthreads();

    int er[4], lr[4];
#pragma unroll
    for (int r = 0; r < 4; r++) {
        const int j = w * 128 + r * 32 + lane;          /* coalesced */
        const int e = indices[c * NPC + j];
        const unsigned mask = __match_any_sync(0xffffffffu, e);
        const int leader = __ffs(mask) - 1;
        const int prefix = __popc(mask & ((1u << lane) - 1u));
        int base = 0;
        if (lane == leader) base = atomicAdd(&wcount[w * 33 + e], __popc(mask));
        base = __shfl_sync(0xffffffffu, base, leader);
        er[r] = e; lr[r] = base + prefix;
    }
    __syncthreads();

    /* warp e scans wcount[*][e] across the 32 warps (lane = warp idx) */
    {
        const int e = w;
        const int val = wcount[lane * 33 + e];
        int incl = val;
#pragma unroll
        for (int d = 1; d < 32; d <<= 1) {
            int n = __shfl_up_sync(0xffffffffu, incl, d);
            if (lane >= d) incl += n;
        }
        woff[lane * 33 + e] = incl - val;
        if (lane == 31) g_counts[c * N_EXPERTS + e] = incl;
    }
    __syncthreads();

#pragma unroll
    for (int r = 0; r < 4; r++) {
        const int j = w * 128 + r * 32 + lane;
        g_rank[c * NPC + j] = woff[w * 33 + er[r]] + lr[r];
    }
}

/* ------------------------------------------------------------------ */
/* Kernel 2: offsets (inline) + row->src table + metadata + counters.
   Threads [0,16384): assignment role (filled rows).
   Threads [16384,49152): row role (tail rows -> -1).                  */
__global__ void __launch_bounds__(256) k_prep(const float* __restrict__ w,
                                              const int* __restrict__ indices,
                                              float* __restrict__ meta,
                                              float* __restrict__ out_cnt) {
    const int t = blockIdx.x * 256 + threadIdx.x;
    if (t < NA) {
        const int c = t >> 12, n = t & (NPC - 1);
        const int tok = n >> 2, kk = n & (TOP_K - 1);
        const int e = indices[t];                        /* coalesced */
        int off = 0;
#pragma unroll
        for (int cc = 0; cc < NUM_CHIPS - 1; cc++)
            if (cc < c) off += g_counts[cc * N_EXPERTS + e];
        const int row = e * MAX_TOK + off + g_rank[t];
        g_srcrow[row] = c * SEQ + tok;
        __nv_bfloat16 wb = __float2bfloat16(w[t]);      /* RNE, matches jnp */
        const int bits = (int)__bfloat16_as_short(wb);  /* sign-extended    */
        float4* m = (float4*)(meta + (size_t)row * META_LEN);
        m[0] = make_float4((float)c, (float)tok, (float)kk, (float)e);
        m[1] = make_float4((float)bits, 0.f, 0.f, 0.f);
        if (t < N_EXPERTS) {                             /* counters section */
            int tot = 0;
#pragma unroll
            for (int cc = 0; cc < NUM_CHIPS; cc++) tot += g_counts[cc * N_EXPERTS + t];
            out_cnt[t] = (float)tot;
        }
    } else {
        const int row = t - NA;
        if (row >= NROWS) return;
        const int e = row >> 10, r = row & (MAX_TOK - 1);
        int tot = 0;
#pragma unroll
        for (int cc = 0; cc < NUM_CHIPS; cc++) tot += g_counts[cc * N_EXPERTS + e];
        if (r < tot) return;                             /* filled above */
        g_srcrow[row] = -1;
        float4* m = (float4*)(meta + (size_t)row * META_LEN);
        const float4 neg = make_float4(-1.f, -1.f, -1.f, -1.f);
        m[0] = neg; m[1] = neg;
    }
}

/* ------------------------------------------------------------------ */
/* Kernel 3: row-per-warp streaming copy with INTERLEAVED row mapping
   (row = r*8192 + gw) so every warp gets a uniform mix of filled and
   zero rows -> no early-retire tail imbalance. One srcrow load per
   row; 4-chunk software pipeline (4 loads then 4 stores) per row.     */
__global__ void __launch_bounds__(COPY_THREADS) k_copy(const float4* __restrict__ x4,
                                                       float4* __restrict__ buf4) {
    const unsigned gw = (blockIdx.x * COPY_THREADS + threadIdx.x) >> 5;  /* global warp */
    const unsigned lane = threadIdx.x & 31;

#pragma unroll
    for (int r = 0; r < ROWS_PER_WARP; r++) {
        const unsigned row = (unsigned)r * TOTAL_WARPS + gw;   /* interleaved */
        const int s = __ldg(&g_srcrow[row]);
        float4* dst = buf4 + row * V4_PER_ROW + lane;
        if (s >= 0) {
            const float4* src = x4 + (unsigned)s * V4_PER_ROW + lane;
#pragma unroll
            for (int ch = 0; ch < 4; ch++) {
                float4 v[4];
#pragma unroll
                for (int u = 0; u < 4; u++)
                    v[u] = __ldg(&src[(ch * 4 + u) * 32]);
#pragma unroll
                for (int u = 0; u < 4; u++)
                    dst[(ch * 4 + u) * 32] = v[u];
            }
        } else {
            const float4 z = make_float4(0.f, 0.f, 0.f, 0.f);
#pragma unroll
            for (int it = 0; it < 16; it++)
                dst[it * 32] = z;
        }
    }
}

/* ------------------------------------------------------------------ */
extern "C" void kernel_launch(void* const* d_in, const int* in_sizes, int n_in,
                              void* d_out, int out_size) {
    const float* x   = (const float*)d_in[0];
    const float* w   = (const float*)d_in[1];
    const int*   idx = (const int*)d_in[2];

    float* out  = (float*)d_out;
    float* buf  = out;                                                   /* 32*1024*2048 */
    float* meta = out + (size_t)NROWS * HIDDEN;                          /* 32*1024*8    */
    float* cnt  = meta + (size_t)NROWS * META_LEN;                       /* 32           */

    k_rank<<<NUM_CHIPS, 1024>>>(idx);
    k_prep<<<(NA + NROWS + 255) / 256, 256>>>(w, idx, meta, cnt);
    k_copy<<<COPY_BLOCKS, COPY_THREADS>>>((const float4*)x, (float4*)buf);
}

// round 7
// speedup vs baseline: 1.1037x; 1.0967x over previous
#include <cuda_runtime.h>
#include <cuda_bf16.h>

#define NUM_CHIPS 4
#define N_EXPERTS 32
#define TOP_K 4
#define SEQ 1024
#define HIDDEN 2048
#define MAX_TOK 1024
#define META_LEN 8
#define NPC (SEQ * TOP_K)            /* 4096 assignments per chip  */
#define NA (NUM_CHIPS * NPC)         /* 16384 total assignments    */
#define NROWS (N_EXPERTS * MAX_TOK)  /* 32768 output rows          */

#define V4_PER_ROW (HIDDEN / 4)      /* 512 float4 per row  */
#define COPY_THREADS 128             /* one block per row; 4 float4/thread */

/* scratch — no allocations allowed */
__device__ int g_counts[NUM_CHIPS * N_EXPERTS];
__device__ int g_rank[NA];       /* assignment -> stable rank within its chip+expert */
__device__ int g_srcrow[NROWS];  /* row -> source token row index, or -1             */

/* ------------------------------------------------------------------ */
/* Kernel 1: stable within-chip rank via warp intrinsics.
   One block per chip, 1024 threads; warp w owns assignments
   [w*128, w*128+128) in 4 rounds of 32 (lane order = flat order).      */
__global__ void __launch_bounds__(1024) k_rank(const int* __restrict__ indices) {
    __shared__ int wcount[32 * 33];   /* [warp][expert], 33-padded */
    __shared__ int woff[32 * 33];
    const int c = blockIdx.x;
    const int tid = threadIdx.x, w = tid >> 5, lane = tid & 31;

    for (int i = tid; i < 32 * 33; i += 1024) wcount[i] = 0;
    __syncthreads();

    int er[4], lr[4];
#pragma unroll
    for (int r = 0; r < 4; r++) {
        const int j = w * 128 + r * 32 + lane;          /* coalesced */
        const int e = indices[c * NPC + j];
        const unsigned mask = __match_any_sync(0xffffffffu, e);
        const int leader = __ffs(mask) - 1;
        const int prefix = __popc(mask & ((1u << lane) - 1u));
        int base = 0;
        if (lane == leader) base = atomicAdd(&wcount[w * 33 + e], __popc(mask));
        base = __shfl_sync(0xffffffffu, base, leader);
        er[r] = e; lr[r] = base + prefix;
    }
    __syncthreads();

    /* warp e scans wcount[*][e] across the 32 warps (lane = warp idx) */
    {
        const int e = w;
        const int val = wcount[lane * 33 + e];
        int incl = val;
#pragma unroll
        for (int d = 1; d < 32; d <<= 1) {
            int n = __shfl_up_sync(0xffffffffu, incl, d);
            if (lane >= d) incl += n;
        }
        woff[lane * 33 + e] = incl - val;
        if (lane == 31) g_counts[c * N_EXPERTS + e] = incl;
    }
    __syncthreads();

#pragma unroll
    for (int r = 0; r < 4; r++) {
        const int j = w * 128 + r * 32 + lane;
        g_rank[c * NPC + j] = woff[w * 33 + er[r]] + lr[r];
    }
}

/* ------------------------------------------------------------------ */
/* Kernel 2: offsets (inline) + row->src table + metadata + counters.
   Threads [0,16384): assignment role (filled rows).
   Threads [16384,49152): row role (tail rows -> -1).                  */
__global__ void __launch_bounds__(256) k_prep(const float* __restrict__ w,
                                              const int* __restrict__ indices,
                                              float* __restrict__ meta,
                                              float* __restrict__ out_cnt) {
    const int t = blockIdx.x * 256 + threadIdx.x;
    if (t < NA) {
        const int c = t >> 12, n = t & (NPC - 1);
        const int tok = n >> 2, kk = n & (TOP_K - 1);
        const int e = indices[t];                        /* coalesced */
        int off = 0;
#pragma unroll
        for (int cc = 0; cc < NUM_CHIPS - 1; cc++)
            if (cc < c) off += g_counts[cc * N_EXPERTS + e];
        const int row = e * MAX_TOK + off + g_rank[t];
        g_srcrow[row] = c * SEQ + tok;
        __nv_bfloat16 wb = __float2bfloat16(w[t]);      /* RNE, matches jnp */
        const int bits = (int)__bfloat16_as_short(wb);  /* sign-extended    */
        float4* m = (float4*)(meta + (size_t)row * META_LEN);
        m[0] = make_float4((float)c, (float)tok, (float)kk, (float)e);
        m[1] = make_float4((float)bits, 0.f, 0.f, 0.f);
        if (t < N_EXPERTS) {                             /* counters section */
            int tot = 0;
#pragma unroll
            for (int cc = 0; cc < NUM_CHIPS; cc++) tot += g_counts[cc * N_EXPERTS + t];
            out_cnt[t] = (float)tot;
        }
    } else {
        const int row = t - NA;
        if (row >= NROWS) return;
        const int e = row >> 10, r = row & (MAX_TOK - 1);
        int tot = 0;
#pragma unroll
        for (int cc = 0; cc < NUM_CHIPS; cc++) tot += g_counts[cc * N_EXPERTS + e];
        if (r < tot) return;                             /* filled above */
        g_srcrow[row] = -1;
        float4* m = (float4*)(meta + (size_t)row * META_LEN);
        const float4 neg = make_float4(-1.f, -1.f, -1.f, -1.f);
        m[0] = neg; m[1] = neg;
    }
}

/* ------------------------------------------------------------------ */
/* Kernel 3: one 128-thread block per output row.
   srcrow loaded once per warp (L1 broadcast, ~1/32 LSU op/element).
   Filled row: 4 independent LDG chains then 4 STGs per thread.
   Zero row: 4 STGs only (no load traffic, no srcrow per-element).
   32768 tiny blocks -> deep wave structure, self-balancing.           */
__global__ void __launch_bounds__(COPY_THREADS) k_copy(const float4* __restrict__ x4,
                                                       float4* __restrict__ buf4) {
    const unsigned row = blockIdx.x;
    const unsigned t = threadIdx.x;
    const int s = __ldg(&g_srcrow[row]);
    float4* dst = buf4 + row * V4_PER_ROW + t;

    if (s >= 0) {
        const float4* src = x4 + (unsigned)s * V4_PER_ROW + t;
        float4 v0 = __ldg(&src[0 * COPY_THREADS]);
        float4 v1 = __ldg(&src[1 * COPY_THREADS]);
        float4 v2 = __ldg(&src[2 * COPY_THREADS]);
        float4 v3 = __ldg(&src[3 * COPY_THREADS]);
        dst[0 * COPY_THREADS] = v0;
        dst[1 * COPY_THREADS] = v1;
        dst[2 * COPY_THREADS] = v2;
        dst[3 * COPY_THREADS] = v3;
    } else {
        const float4 z = make_float4(0.f, 0.f, 0.f, 0.f);
        dst[0 * COPY_THREADS] = z;
        dst[1 * COPY_THREADS] = z;
        dst[2 * COPY_THREADS] = z;
        dst[3 * COPY_THREADS] = z;
    }
}

/* ------------------------------------------------------------------ */
extern "C" void kernel_launch(void* const* d_in, const int* in_sizes, int n_in,
                              void* d_out, int out_size) {
    const float* x   = (const float*)d_in[0];
    const float* w   = (const float*)d_in[1];
    const int*   idx = (const int*)d_in[2];

    float* out  = (float*)d_out;
    float* buf  = out;                                                   /* 32*1024*2048 */
    float* meta = out + (size_t)NROWS * HIDDEN;                          /* 32*1024*8    */
    float* cnt  = meta + (size_t)NROWS * META_LEN;                       /* 32           */

    k_rank<<<NUM_CHIPS, 1024>>>(idx);
    k_prep<<<(NA + NROWS + 255) / 256, 256>>>(w, idx, meta, cnt);
    k_copy<<<NROWS, COPY_THREADS>>>((const float4*)x, (float4*)buf);
}